// round 15
// baseline (speedup 1.0000x reference)
#include <cuda_runtime.h>
#include <math.h>

#define BB   8
#define SS   512
#define HH   1024
#define NHH  8
#define DHH  128
#define MM   (BB*SS)
#define IN3  3072
#define R2   1024
#define HD   512
#define G4   2048
#define INV_SCALE 0.051031036307982884f  /* 1/sqrt(128*3) */
#define TP2  20                          /* smem row pitch (floats) */

__device__ float g_h1[MM*HH];
__device__ float g_qkv[MM*3*HH];
__device__ float g_posk[R2*HH];
__device__ float g_posq[R2*HH];
__device__ float g_scores[BB*NHH*SS*SS];
__device__ float g_ctx2[MM*HH];
__device__ float g_t1[MM*IN3];
__device__ float g_y[MM*HH];
__device__ float g_h2[MM*HH];
__device__ float g_h3[MM*HH];
__device__ float g_xw[2*MM*G4];
__device__ float g_hseq[2*513*BB*HD];
__device__ unsigned int g_bar2[2];

__device__ __forceinline__ unsigned tf32cvt(float x)
{
    unsigned r;
    asm("cvt.rna.tf32.f32 %0, %1;" : "=r"(r) : "f"(x));
    return r;
}

// Tensor-core GEMM: C = A[M,K]*B[N,K]^T, mma m16n8k8 tf32 (rna cvt at fragment load).
// 128x128 block tile, 8 warps (2x4), warp 64x32. K-tile 16, 3-stage cp.async ring.
__global__ void __launch_bounds__(256, 2)
tgemm_kernel(const float* __restrict__ A, const float* __restrict__ Bw,
             float* __restrict__ C, int Md, int Nd, int Kd,
             const float* __restrict__ bias, const float* __restrict__ bias2,
             const float* __restrict__ res, float scale, int act)
{
    extern __shared__ float sm[];
    float* Asm = sm;                       // [3][128][TP2]
    float* Bsm = sm + 3 * 128 * TP2;       // [3][128][TP2]
    int tid = threadIdx.x;
    int m0 = blockIdx.y << 7, n0 = blockIdx.x << 7;
    int warp = tid >> 5, lane = tid & 31;
    int wm = (warp >> 2) << 6;
    int wn = (warp & 3) << 5;
    int g = lane >> 2, tg = lane & 3;

    float c[4][4][4];
#pragma unroll
    for (int mt = 0; mt < 4; mt++)
#pragma unroll
        for (int nt = 0; nt < 4; nt++)
#pragma unroll
            for (int i = 0; i < 4; i++) c[mt][nt][i] = 0.f;

    auto load_tile = [&](int st, int k0) {
#pragma unroll
        for (int i = 0; i < 2; i++) {
            int ch = tid + (i << 8);
            int row = ch >> 2, c4 = (ch & 3) << 2;
            unsigned sa = (unsigned)__cvta_generic_to_shared(&Asm[(st * 128 + row) * TP2 + c4]);
            asm volatile("cp.async.cg.shared.global [%0], [%1], 16;"
                         :: "r"(sa), "l"(A + (long)(m0 + row) * Kd + k0 + c4));
            unsigned sb = (unsigned)__cvta_generic_to_shared(&Bsm[(st * 128 + row) * TP2 + c4]);
            asm volatile("cp.async.cg.shared.global [%0], [%1], 16;"
                         :: "r"(sb), "l"(Bw + (long)(n0 + row) * Kd + k0 + c4));
        }
        asm volatile("cp.async.commit_group;");
    };

    int nk = Kd >> 4;
    load_tile(0, 0);
    load_tile(1, 16);
    for (int kt = 0; kt < nk; kt++) {
        asm volatile("cp.async.wait_group 1;");
        __syncthreads();
        if (kt + 2 < nk) load_tile((kt + 2) % 3, (kt + 2) << 4);
        const float* As = Asm + (long)(kt % 3) * 128 * TP2;
        const float* Bs = Bsm + (long)(kt % 3) * 128 * TP2;
#pragma unroll
        for (int kc = 0; kc < 2; kc++) {
            int kb = kc << 3;
            unsigned af[4][4], bf[4][2];
#pragma unroll
            for (int mt = 0; mt < 4; mt++) {
                int m = wm + (mt << 4);
                af[mt][0] = tf32cvt(As[(m + g) * TP2 + kb + tg]);
                af[mt][1] = tf32cvt(As[(m + g + 8) * TP2 + kb + tg]);
                af[mt][2] = tf32cvt(As[(m + g) * TP2 + kb + tg + 4]);
                af[mt][3] = tf32cvt(As[(m + g + 8) * TP2 + kb + tg + 4]);
            }
#pragma unroll
            for (int nt = 0; nt < 4; nt++) {
                int n = wn + (nt << 3);
                bf[nt][0] = tf32cvt(Bs[(n + g) * TP2 + kb + tg]);
                bf[nt][1] = tf32cvt(Bs[(n + g) * TP2 + kb + tg + 4]);
            }
#pragma unroll
            for (int mt = 0; mt < 4; mt++)
#pragma unroll
                for (int nt = 0; nt < 4; nt++) {
                    asm volatile(
                        "mma.sync.aligned.m16n8k8.row.col.f32.tf32.tf32.f32 "
                        "{%0,%1,%2,%3}, {%4,%5,%6,%7}, {%8,%9}, {%0,%1,%2,%3};"
                        : "+f"(c[mt][nt][0]), "+f"(c[mt][nt][1]),
                          "+f"(c[mt][nt][2]), "+f"(c[mt][nt][3])
                        : "r"(af[mt][0]), "r"(af[mt][1]), "r"(af[mt][2]), "r"(af[mt][3]),
                          "r"(bf[nt][0]), "r"(bf[nt][1]));
                }
        }
        __syncthreads();
    }

#pragma unroll
    for (int mt = 0; mt < 4; mt++) {
#pragma unroll
        for (int nt = 0; nt < 4; nt++) {
#pragma unroll
            for (int i = 0; i < 4; i++) {
                int m = m0 + wm + (mt << 4) + g + ((i >> 1) << 3);
                int n = n0 + wn + (nt << 3) + (tg << 1) + (i & 1);
                float v = c[mt][nt][i];
                if (bias)  v += bias[n];
                if (bias2) v += bias2[n];
                if (res)   v += res[(long)m * Nd + n];
                v *= scale;
                if (act) v = 0.5f * v * (1.f + erff(v * 0.70710678118654752f));
                C[(long)m * Nd + n] = v;
            }
        }
    }
}

// LN with optional fused add (pos-emb broadcast over batch via addMod)
__global__ void ln_kernel(const float* __restrict__ in, const float* __restrict__ add,
                          int addMod, const float* __restrict__ gw,
                          const float* __restrict__ bw, float* __restrict__ out)
{
    int row = blockIdx.x;
    const float* xp = in + (long)row * HH;
    const float* ap = add ? add + (long)(row % addMod) * HH : (const float*)0;
    int tid = threadIdx.x;
    float v[4]; float s = 0.f, sq = 0.f;
#pragma unroll
    for (int i = 0; i < 4; i++) {
        int c = tid + (i << 8);
        float t = xp[c];
        if (ap) t += ap[c];
        v[i] = t; s += t; sq += t * t;
    }
#pragma unroll
    for (int o = 16; o > 0; o >>= 1) {
        s  += __shfl_xor_sync(0xffffffffu, s, o);
        sq += __shfl_xor_sync(0xffffffffu, sq, o);
    }
    __shared__ float red[18];
    int w = tid >> 5, l = tid & 31;
    if (l == 0) { red[w] = s; red[8 + w] = sq; }
    __syncthreads();
    if (tid == 0) {
        float ts = 0.f, tq = 0.f;
#pragma unroll
        for (int i = 0; i < 8; i++) { ts += red[i]; tq += red[8 + i]; }
        float mean = ts * (1.f / HH);
        float var  = tq * (1.f / HH) - mean * mean;
        red[16] = mean; red[17] = rsqrtf(var + 1e-7f);
    }
    __syncthreads();
    float mean = red[16], rstd = red[17];
    float* op = out + (long)row * HH;
#pragma unroll
    for (int i = 0; i < 4; i++) {
        int c = tid + (i << 8);
        op[c] = (v[i] - mean) * rstd * gw[c] + bw[c];
    }
}

// Fused scores + c2p + p2c + softmax, coalesced warp-per-k.
__global__ void attn_kernel(const float* __restrict__ qkv, const float* __restrict__ posk,
                            const float* __restrict__ posq, float* __restrict__ scores,
                            const float* __restrict__ qb)
{
    int row = blockIdx.x;
    int z = row >> 9, q = row & 511;
    int b = z >> 3, h = z & 7;
    int tid = threadIdx.x;
    int w = tid >> 5, lane = tid & 31;
    __shared__ float qs[DHH];
    __shared__ float sc[SS];
    __shared__ float red[17];
    const float* qkvq = qkv + ((long)(b * SS + q)) * (3 * HH) + h * DHH;
    if (tid < DHH) qs[tid] = (qkvq[tid] + qb[h * DHH + tid]) * INV_SCALE;
    __syncthreads();
    float4 qv = ((const float4*)qs)[lane];

#pragma unroll 2
    for (int i = 0; i < 64; i++) {
        int k = (w << 6) + i;
        int rel = q - k + 512;
        float4 kv = ((const float4*)(qkv + ((long)(b * SS + k)) * (3 * HH) + HH + h * DHH))[lane];
        float4 cv = ((const float4*)(posk + (long)rel * HH + h * DHH))[lane];
        float4 pv = ((const float4*)(posq + (long)rel * HH + h * DHH))[lane];
        float s = qv.x * (kv.x + cv.x) + kv.x * pv.x
                + qv.y * (kv.y + cv.y) + kv.y * pv.y
                + qv.z * (kv.z + cv.z) + kv.z * pv.z
                + qv.w * (kv.w + cv.w) + kv.w * pv.w;
#pragma unroll
        for (int o = 16; o > 0; o >>= 1) s += __shfl_xor_sync(0xffffffffu, s, o);
        if (lane == 0) sc[k] = s;
    }
    __syncthreads();

    float v0 = sc[tid], v1 = sc[tid + 256];
    float mx = fmaxf(v0, v1);
#pragma unroll
    for (int o = 16; o > 0; o >>= 1) mx = fmaxf(mx, __shfl_xor_sync(0xffffffffu, mx, o));
    if (lane == 0) red[w] = mx;
    __syncthreads();
    if (tid == 0) {
        float m2 = red[0];
#pragma unroll
        for (int i = 1; i < 8; i++) m2 = fmaxf(m2, red[i]);
        red[16] = m2;
    }
    __syncthreads();
    mx = red[16];
    float e0 = __expf(v0 - mx), e1 = __expf(v1 - mx);
    float s = e0 + e1;
#pragma unroll
    for (int o = 16; o > 0; o >>= 1) s += __shfl_xor_sync(0xffffffffu, s, o);
    __syncthreads();
    if (lane == 0) red[w] = s;
    __syncthreads();
    if (tid == 0) {
        float t = 0.f;
#pragma unroll
        for (int i = 0; i < 8; i++) t += red[i];
        red[16] = 1.f / t;
    }
    __syncthreads();
    float inv = red[16];
    float* srow = scores + (long)row * SS;
    srow[tid] = e0 * inv;
    srow[tid + 256] = e1 * inv;
}

// ctx2[b,q,h*128+d] = sum_k probs[z,q,k] * qkv_v[b,k,h*128+d]  + vb
__global__ void ctx_naive_kernel(const float* __restrict__ qkv, const float* __restrict__ scores,
                                 float* __restrict__ ctx2, const float* __restrict__ vb)
{
    __shared__ float ps[SS];
    int row = blockIdx.x;
    int z = row >> 9, q = row & 511;
    int b = z >> 3, h = z & 7;
    int tid = threadIdx.x;
    const float* srow = scores + (long)row * SS;
    for (int k = tid; k < SS; k += 128) ps[k] = srow[k];
    __syncthreads();
    int c = h * DHH + tid;
    const float* vp = qkv + (long)b * SS * (3 * HH) + 2 * HH + c;
    float acc = 0.f;
#pragma unroll 4
    for (int k = 0; k < SS; k++)
        acc = fmaf(ps[k], vp[(long)k * (3 * HH)], acc);
    acc += vb[c];
    ctx2[((long)(b * SS + q)) * HH + c] = acc;
}

// Persistent wavefront LSTM: 128 blocks, per-direction barriers, float4 weight/h loads.
__global__ void LSTMDisentangledAttention_15049565405471_kernel(
    const float* __restrict__ xw,
    const float* __restrict__ WhhF,
    const float* __restrict__ WhhR,
    float* __restrict__ out)
{
    extern __shared__ float sm[];
    float* Wsh = sm;              // [128][32][4]
    float* hs  = sm + HD * 32;    // [8][512]
    int tid = threadIdx.x, blk = blockIdx.x;
    int dir = blk >> 6;
    int u0  = (blk & 63) << 3;
    int b = tid >> 5, lane = tid & 31;
    int ui = lane >> 2, gate = lane & 3;
    int r = (gate << 9) + u0 + ui;
    const float* Whh = dir ? WhhR : WhhF;
    const float* xwd = xw + (long)dir * MM * G4;
    float* seq = g_hseq + (long)dir * 513 * (BB * HD);
    unsigned int* bar = &g_bar2[dir];

    for (int idx = tid; idx < HD * 32; idx += 256) {
        int jb = idx >> 7;
        int l  = (idx >> 2) & 31;
        int jj = idx & 3;
        int j  = (jb << 2) + jj;
        int rl = ((l & 3) << 9) + u0 + (l >> 2);
        Wsh[idx] = Whh[(long)rl * HD + j];
    }

    float c = 0.f;
    __syncthreads();

    const float4* W4 = (const float4*)Wsh;
    for (int t = 0; t < SS; t++) {
        int sI = dir ? (SS - 1 - t) : t;
        const float* hrd = seq + (long)t * (BB * HD);
        for (int idx = tid; idx < BB * HD; idx += 256)
            hs[idx] = hrd[idx];
        __syncthreads();

        float acc = xwd[((long)((b << 9) + sI)) * G4 + r];
        const float4* h4 = (const float4*)(hs + (b << 9));
#pragma unroll 8
        for (int jb = 0; jb < 128; jb++) {
            float4 wv = W4[(jb << 5) + lane];
            float4 hv = h4[jb];
            acc = fmaf(wv.x, hv.x, acc);
            acc = fmaf(wv.y, hv.y, acc);
            acc = fmaf(wv.z, hv.z, acc);
            acc = fmaf(wv.w, hv.w, acc);
        }

        int base = lane & ~3;
        float vi = __shfl_sync(0xffffffffu, acc, base + 0);
        float vf = __shfl_sync(0xffffffffu, acc, base + 1);
        float vg = __shfl_sync(0xffffffffu, acc, base + 2);
        float vo = __shfl_sync(0xffffffffu, acc, base + 3);
        float ig = 1.f / (1.f + __expf(-vi));
        float fg = 1.f / (1.f + __expf(-vf));
        float gg = tanhf(vg);
        float og = 1.f / (1.f + __expf(-vo));
        c = fg * c + ig * gg;
        float hv = og * tanhf(c);
        if (gate == 0) {
            int u = u0 + ui;
            seq[(long)(t + 1) * (BB * HD) + (b << 9) + u] = hv;
            out[((long)((b << 9) + sI)) * HH + (dir << 9) + u] = hv;
        }
        __threadfence();
        __syncthreads();
        if (tid == 0) {
            atomicAdd(bar, 1u);
            unsigned target = (unsigned)(t + 1) * 64u;
            while (*((volatile unsigned int*)bar) < target) { }
            __threadfence();
        }
        __syncthreads();
    }
}

extern "C" void kernel_launch(void* const* d_in, const int* in_sizes, int n_in,
                              void* d_out, int out_size)
{
    (void)in_sizes; (void)n_in; (void)out_size;
    const float* x       = (const float*)d_in[0];
    const float* pos_emb = (const float*)d_in[1];
    const float* emb_g   = (const float*)d_in[2];
    const float* emb_b   = (const float*)d_in[3];
    const float* in_w    = (const float*)d_in[4];
    const float* q_bias  = (const float*)d_in[5];
    const float* v_bias  = (const float*)d_in[6];
    const float* rel_emb = (const float*)d_in[7];
    const float* posk_w  = (const float*)d_in[8];
    const float* posq_w  = (const float*)d_in[9];
    const float* posq_b  = (const float*)d_in[10];
    const float* ao_w    = (const float*)d_in[11];
    const float* ao_b    = (const float*)d_in[12];
    const float* aln_g   = (const float*)d_in[13];
    const float* aln_b   = (const float*)d_in[14];
    const float* it_w    = (const float*)d_in[15];
    const float* it_b    = (const float*)d_in[16];
    const float* fo_w    = (const float*)d_in[17];
    const float* fo_b    = (const float*)d_in[18];
    const float* fln_g   = (const float*)d_in[19];
    const float* fln_b   = (const float*)d_in[20];
    const float* Wih_f   = (const float*)d_in[21];
    const float* Whh_f   = (const float*)d_in[22];
    const float* bih_f   = (const float*)d_in[23];
    const float* bhh_f   = (const float*)d_in[24];
    const float* Wih_r   = (const float*)d_in[25];
    const float* Whh_r   = (const float*)d_in[26];
    const float* bih_r   = (const float*)d_in[27];
    const float* bhh_r   = (const float*)d_in[28];
    float* out = (float*)d_out;

    float *h1, *qkv, *posk, *posq, *scores, *ctx2, *t1, *y, *h2, *h3, *xw;
    void  *barp, *seqp;
    cudaGetSymbolAddress((void**)&h1,     g_h1);
    cudaGetSymbolAddress((void**)&qkv,    g_qkv);
    cudaGetSymbolAddress((void**)&posk,   g_posk);
    cudaGetSymbolAddress((void**)&posq,   g_posq);
    cudaGetSymbolAddress((void**)&scores, g_scores);
    cudaGetSymbolAddress((void**)&ctx2,   g_ctx2);
    cudaGetSymbolAddress((void**)&t1,     g_t1);
    cudaGetSymbolAddress((void**)&y,      g_y);
    cudaGetSymbolAddress((void**)&h2,     g_h2);
    cudaGetSymbolAddress((void**)&h3,     g_h3);
    cudaGetSymbolAddress((void**)&xw,     g_xw);
    cudaGetSymbolAddress(&barp,           g_bar2);
    cudaGetSymbolAddress(&seqp,           g_hseq);

    int gsmem = 3 * 2 * 128 * TP2 * 4;   // 61440 B
    cudaFuncSetAttribute(tgemm_kernel, cudaFuncAttributeMaxDynamicSharedMemorySize, gsmem);

    // 1. h1 = LN(x + pos_emb)
    ln_kernel<<<MM, 256>>>(x, pos_emb, SS, emb_g, emb_b, h1);
    // 2. qkv = h1 @ in_w^T
    tgemm_kernel<<<dim3(IN3/128, MM/128), 256, gsmem>>>(h1, in_w, qkv, MM, IN3, HH,
        0, 0, 0, 1.f, 0);
    // 3. pos tables (pos_q pre-scaled)
    tgemm_kernel<<<dim3(HH/128, R2/128), 256, gsmem>>>(rel_emb, posk_w, posk, R2, HH, HH,
        0, 0, 0, 1.f, 0);
    tgemm_kernel<<<dim3(HH/128, R2/128), 256, gsmem>>>(rel_emb, posq_w, posq, R2, HH, HH,
        posq_b, 0, 0, INV_SCALE, 0);
    // 4. fused scores + c2p + p2c + softmax
    attn_kernel<<<BB*NHH*SS, 256>>>(qkv, posk, posq, scores, q_bias);
    // 5. ctx directly from qkv
    ctx_naive_kernel<<<BB*NHH*SS, 128>>>(qkv, scores, ctx2, v_bias);
    // 6. attn out + residual + LN
    tgemm_kernel<<<dim3(HH/128, MM/128), 256, gsmem>>>(ctx2, ao_w, y, MM, HH, HH,
        ao_b, 0, h1, 1.f, 0);
    ln_kernel<<<MM, 256>>>(y, 0, 1, aln_g, aln_b, h2);
    // 7. FFN
    tgemm_kernel<<<dim3(IN3/128, MM/128), 256, gsmem>>>(h2, it_w, t1, MM, IN3, HH,
        it_b, 0, 0, 1.f, 1);
    tgemm_kernel<<<dim3(HH/128, MM/128), 256, gsmem>>>(t1, fo_w, y, MM, HH, IN3,
        fo_b, 0, h2, 1.f, 0);
    ln_kernel<<<MM, 256>>>(y, 0, 1, fln_g, fln_b, h3);
    // 8. LSTM input projections
    tgemm_kernel<<<dim3(G4/128, MM/128), 256, gsmem>>>(h3, Wih_f, xw, MM, G4, HH,
        bih_f, bhh_f, 0, 1.f, 0);
    tgemm_kernel<<<dim3(G4/128, MM/128), 256, gsmem>>>(h3, Wih_r, xw + (long)MM*G4, MM, G4, HH,
        bih_r, bhh_r, 0, 1.f, 0);
    // 9. persistent wavefront LSTM
    cudaMemsetAsync(barp, 0, 2 * sizeof(unsigned int), 0);
    cudaMemsetAsync(seqp, 0, sizeof(float) * BB * HD, 0);
    cudaMemsetAsync((char*)seqp + sizeof(float) * 513 * BB * HD, 0, sizeof(float) * BB * HD, 0);
    int lsmem = HD * 32 * 4 + BB * HD * 4;
    cudaFuncSetAttribute(LSTMDisentangledAttention_15049565405471_kernel,
                         cudaFuncAttributeMaxDynamicSharedMemorySize, lsmem);
    LSTMDisentangledAttention_15049565405471_kernel<<<128, 256, lsmem>>>(xw, Whh_f, Whh_r, out);
}

// round 16
// speedup vs baseline: 1.0743x; 1.0743x over previous
#include <cuda_runtime.h>
#include <cuda_fp16.h>
#include <math.h>

#define BB   8
#define SS   512
#define HH   1024
#define NHH  8
#define DHH  128
#define MM   (BB*SS)
#define IN3  3072
#define R2   1024
#define HD   512
#define G4   2048
#define INV_SCALE 0.051031036307982884f  /* 1/sqrt(128*3) */
#define PH   40                          /* smem pitch in halfs (20 words): banks 20g+tg, conflict-free */

__device__ float g_h1[MM*HH];
__device__ float g_qkv[MM*3*HH];
__device__ float g_posk[R2*HH];
__device__ float g_posq[R2*HH];
__device__ float g_scores[BB*NHH*SS*SS];
__device__ float g_ctx2[MM*HH];
__device__ float g_t1[MM*IN3];
__device__ float g_y[MM*HH];
__device__ float g_h2[MM*HH];
__device__ float g_h3[MM*HH];
__device__ float g_xw[2*MM*G4];
__device__ float g_hseq[2*513*BB*HD];
__device__ unsigned int g_bar2[2];

// Tensor-core GEMM: C = A[M,K]*B[N,K]^T via mma.m16n8k16 f16 (fp32 accum).
// 128x128 block tile, 8 warps (2x4), warp 64x32. K-tile 16, register-staged
// fp32->fp16 conversion (once per element), prefetch one tile ahead.
__global__ void __launch_bounds__(256, 2)
tgemm_kernel(const float* __restrict__ A, const float* __restrict__ Bw,
             float* __restrict__ C, int Md, int Nd, int Kd,
             const float* __restrict__ bias, const float* __restrict__ bias2,
             const float* __restrict__ res, float scale, int act)
{
    extern __shared__ char smraw[];
    __half* Ah = (__half*)smraw;                       // [128][PH]
    __half* Bh = (__half*)(smraw + 128 * PH * 2);      // [128][PH]
    const unsigned* Au = (const unsigned*)Ah;
    const unsigned* Bu = (const unsigned*)Bh;
    int tid = threadIdx.x;
    int m0 = blockIdx.y << 7, n0 = blockIdx.x << 7;
    int warp = tid >> 5, lane = tid & 31;
    int wm = (warp >> 2) << 6;
    int wn = (warp & 3) << 5;
    int g = lane >> 2, tg = lane & 3;

    float c[4][4][4];
#pragma unroll
    for (int mt = 0; mt < 4; mt++)
#pragma unroll
        for (int nt = 0; nt < 4; nt++)
#pragma unroll
            for (int i = 0; i < 4; i++) c[mt][nt][i] = 0.f;

    float4 pa[2], pb[2];
    auto ldg_tile = [&](int k0) {
#pragma unroll
        for (int i = 0; i < 2; i++) {
            int ch = tid + (i << 8);
            int row = ch >> 2, kq = (ch & 3) << 2;
            pa[i] = *(const float4*)(A  + (long)(m0 + row) * Kd + k0 + kq);
            pb[i] = *(const float4*)(Bw + (long)(n0 + row) * Kd + k0 + kq);
        }
    };
    auto sts_tile = [&]() {
#pragma unroll
        for (int i = 0; i < 2; i++) {
            int ch = tid + (i << 8);
            int row = ch >> 2, kq = (ch & 3) << 2;
            __half2* da = (__half2*)(Ah + row * PH + kq);
            da[0] = __floats2half2_rn(pa[i].x, pa[i].y);
            da[1] = __floats2half2_rn(pa[i].z, pa[i].w);
            __half2* db = (__half2*)(Bh + row * PH + kq);
            db[0] = __floats2half2_rn(pb[i].x, pb[i].y);
            db[1] = __floats2half2_rn(pb[i].z, pb[i].w);
        }
    };

    int nk = Kd >> 4;
    ldg_tile(0);
    for (int kt = 0; kt < nk; kt++) {
        if (kt) __syncthreads();           // prior compute done before overwrite
        sts_tile();
        if (kt + 1 < nk) ldg_tile((kt + 1) << 4);   // prefetch (latency hidden by compute)
        __syncthreads();

        unsigned af[4][4], bf[4][2];
#pragma unroll
        for (int mt = 0; mt < 4; mt++) {
            int r = wm + (mt << 4) + g;
            af[mt][0] = Au[r * (PH / 2) + tg];
            af[mt][1] = Au[(r + 8) * (PH / 2) + tg];
            af[mt][2] = Au[r * (PH / 2) + tg + 4];
            af[mt][3] = Au[(r + 8) * (PH / 2) + tg + 4];
        }
#pragma unroll
        for (int nt = 0; nt < 4; nt++) {
            int r = wn + (nt << 3) + g;
            bf[nt][0] = Bu[r * (PH / 2) + tg];
            bf[nt][1] = Bu[r * (PH / 2) + tg + 4];
        }
#pragma unroll
        for (int mt = 0; mt < 4; mt++)
#pragma unroll
            for (int nt = 0; nt < 4; nt++) {
                asm volatile(
                    "mma.sync.aligned.m16n8k16.row.col.f32.f16.f16.f32 "
                    "{%0,%1,%2,%3}, {%4,%5,%6,%7}, {%8,%9}, {%0,%1,%2,%3};"
                    : "+f"(c[mt][nt][0]), "+f"(c[mt][nt][1]),
                      "+f"(c[mt][nt][2]), "+f"(c[mt][nt][3])
                    : "r"(af[mt][0]), "r"(af[mt][1]), "r"(af[mt][2]), "r"(af[mt][3]),
                      "r"(bf[nt][0]), "r"(bf[nt][1]));
            }
    }

#pragma unroll
    for (int mt = 0; mt < 4; mt++) {
#pragma unroll
        for (int nt = 0; nt < 4; nt++) {
#pragma unroll
            for (int i = 0; i < 4; i++) {
                int m = m0 + wm + (mt << 4) + g + ((i >> 1) << 3);
                int n = n0 + wn + (nt << 3) + (tg << 1) + (i & 1);
                float v = c[mt][nt][i];
                if (bias)  v += bias[n];
                if (bias2) v += bias2[n];
                if (res)   v += res[(long)m * Nd + n];
                v *= scale;
                if (act) v = 0.5f * v * (1.f + erff(v * 0.70710678118654752f));
                C[(long)m * Nd + n] = v;
            }
        }
    }
}

// LN with optional fused add (pos-emb broadcast over batch via addMod)
__global__ void ln_kernel(const float* __restrict__ in, const float* __restrict__ add,
                          int addMod, const float* __restrict__ gw,
                          const float* __restrict__ bw, float* __restrict__ out)
{
    int row = blockIdx.x;
    const float* xp = in + (long)row * HH;
    const float* ap = add ? add + (long)(row % addMod) * HH : (const float*)0;
    int tid = threadIdx.x;
    float v[4]; float s = 0.f, sq = 0.f;
#pragma unroll
    for (int i = 0; i < 4; i++) {
        int c = tid + (i << 8);
        float t = xp[c];
        if (ap) t += ap[c];
        v[i] = t; s += t; sq += t * t;
    }
#pragma unroll
    for (int o = 16; o > 0; o >>= 1) {
        s  += __shfl_xor_sync(0xffffffffu, s, o);
        sq += __shfl_xor_sync(0xffffffffu, sq, o);
    }
    __shared__ float red[18];
    int w = tid >> 5, l = tid & 31;
    if (l == 0) { red[w] = s; red[8 + w] = sq; }
    __syncthreads();
    if (tid == 0) {
        float ts = 0.f, tq = 0.f;
#pragma unroll
        for (int i = 0; i < 8; i++) { ts += red[i]; tq += red[8 + i]; }
        float mean = ts * (1.f / HH);
        float var  = tq * (1.f / HH) - mean * mean;
        red[16] = mean; red[17] = rsqrtf(var + 1e-7f);
    }
    __syncthreads();
    float mean = red[16], rstd = red[17];
    float* op = out + (long)row * HH;
#pragma unroll
    for (int i = 0; i < 4; i++) {
        int c = tid + (i << 8);
        op[c] = (v[i] - mean) * rstd * gw[c] + bw[c];
    }
}

// Fused scores + c2p + p2c + softmax, coalesced warp-per-k.
__global__ void attn_kernel(const float* __restrict__ qkv, const float* __restrict__ posk,
                            const float* __restrict__ posq, float* __restrict__ scores,
                            const float* __restrict__ qb)
{
    int row = blockIdx.x;
    int z = row >> 9, q = row & 511;
    int b = z >> 3, h = z & 7;
    int tid = threadIdx.x;
    int w = tid >> 5, lane = tid & 31;
    __shared__ float qs[DHH];
    __shared__ float sc[SS];
    __shared__ float red[17];
    const float* qkvq = qkv + ((long)(b * SS + q)) * (3 * HH) + h * DHH;
    if (tid < DHH) qs[tid] = (qkvq[tid] + qb[h * DHH + tid]) * INV_SCALE;
    __syncthreads();
    float4 qv = ((const float4*)qs)[lane];

#pragma unroll 2
    for (int i = 0; i < 64; i++) {
        int k = (w << 6) + i;
        int rel = q - k + 512;
        float4 kv = ((const float4*)(qkv + ((long)(b * SS + k)) * (3 * HH) + HH + h * DHH))[lane];
        float4 cv = ((const float4*)(posk + (long)rel * HH + h * DHH))[lane];
        float4 pv = ((const float4*)(posq + (long)rel * HH + h * DHH))[lane];
        float s = qv.x * (kv.x + cv.x) + kv.x * pv.x
                + qv.y * (kv.y + cv.y) + kv.y * pv.y
                + qv.z * (kv.z + cv.z) + kv.z * pv.z
                + qv.w * (kv.w + cv.w) + kv.w * pv.w;
#pragma unroll
        for (int o = 16; o > 0; o >>= 1) s += __shfl_xor_sync(0xffffffffu, s, o);
        if (lane == 0) sc[k] = s;
    }
    __syncthreads();

    float v0 = sc[tid], v1 = sc[tid + 256];
    float mx = fmaxf(v0, v1);
#pragma unroll
    for (int o = 16; o > 0; o >>= 1) mx = fmaxf(mx, __shfl_xor_sync(0xffffffffu, mx, o));
    if (lane == 0) red[w] = mx;
    __syncthreads();
    if (tid == 0) {
        float m2 = red[0];
#pragma unroll
        for (int i = 1; i < 8; i++) m2 = fmaxf(m2, red[i]);
        red[16] = m2;
    }
    __syncthreads();
    mx = red[16];
    float e0 = __expf(v0 - mx), e1 = __expf(v1 - mx);
    float s = e0 + e1;
#pragma unroll
    for (int o = 16; o > 0; o >>= 1) s += __shfl_xor_sync(0xffffffffu, s, o);
    __syncthreads();
    if (lane == 0) red[w] = s;
    __syncthreads();
    if (tid == 0) {
        float t = 0.f;
#pragma unroll
        for (int i = 0; i < 8; i++) t += red[i];
        red[16] = 1.f / t;
    }
    __syncthreads();
    float inv = red[16];
    float* srow = scores + (long)row * SS;
    srow[tid] = e0 * inv;
    srow[tid + 256] = e1 * inv;
}

// ctx2[b,q,h*128+d] = sum_k probs[z,q,k] * qkv_v[b,k,h*128+d]  + vb
__global__ void ctx_naive_kernel(const float* __restrict__ qkv, const float* __restrict__ scores,
                                 float* __restrict__ ctx2, const float* __restrict__ vb)
{
    __shared__ float ps[SS];
    int row = blockIdx.x;
    int z = row >> 9, q = row & 511;
    int b = z >> 3, h = z & 7;
    int tid = threadIdx.x;
    const float* srow = scores + (long)row * SS;
    for (int k = tid; k < SS; k += 128) ps[k] = srow[k];
    __syncthreads();
    int c = h * DHH + tid;
    const float* vp = qkv + (long)b * SS * (3 * HH) + 2 * HH + c;
    float acc = 0.f;
#pragma unroll 4
    for (int k = 0; k < SS; k++)
        acc = fmaf(ps[k], vp[(long)k * (3 * HH)], acc);
    acc += vb[c];
    ctx2[((long)(b * SS + q)) * HH + c] = acc;
}

// Persistent wavefront LSTM: 128 blocks, per-direction barriers, float4 weight/h loads.
__global__ void LSTMDisentangledAttention_15049565405471_kernel(
    const float* __restrict__ xw,
    const float* __restrict__ WhhF,
    const float* __restrict__ WhhR,
    float* __restrict__ out)
{
    extern __shared__ float sm[];
    float* Wsh = sm;              // [128][32][4]
    float* hs  = sm + HD * 32;    // [8][512]
    int tid = threadIdx.x, blk = blockIdx.x;
    int dir = blk >> 6;
    int u0  = (blk & 63) << 3;
    int b = tid >> 5, lane = tid & 31;
    int ui = lane >> 2, gate = lane & 3;
    int r = (gate << 9) + u0 + ui;
    const float* Whh = dir ? WhhR : WhhF;
    const float* xwd = xw + (long)dir * MM * G4;
    float* seq = g_hseq + (long)dir * 513 * (BB * HD);
    unsigned int* bar = &g_bar2[dir];

    for (int idx = tid; idx < HD * 32; idx += 256) {
        int jb = idx >> 7;
        int l  = (idx >> 2) & 31;
        int jj = idx & 3;
        int j  = (jb << 2) + jj;
        int rl = ((l & 3) << 9) + u0 + (l >> 2);
        Wsh[idx] = Whh[(long)rl * HD + j];
    }

    float c = 0.f;
    __syncthreads();

    const float4* W4 = (const float4*)Wsh;
    for (int t = 0; t < SS; t++) {
        int sI = dir ? (SS - 1 - t) : t;
        const float* hrd = seq + (long)t * (BB * HD);
        for (int idx = tid; idx < BB * HD; idx += 256)
            hs[idx] = hrd[idx];
        __syncthreads();

        float acc = xwd[((long)((b << 9) + sI)) * G4 + r];
        const float4* h4 = (const float4*)(hs + (b << 9));
#pragma unroll 8
        for (int jb = 0; jb < 128; jb++) {
            float4 wv = W4[(jb << 5) + lane];
            float4 hv = h4[jb];
            acc = fmaf(wv.x, hv.x, acc);
            acc = fmaf(wv.y, hv.y, acc);
            acc = fmaf(wv.z, hv.z, acc);
            acc = fmaf(wv.w, hv.w, acc);
        }

        int base = lane & ~3;
        float vi = __shfl_sync(0xffffffffu, acc, base + 0);
        float vf = __shfl_sync(0xffffffffu, acc, base + 1);
        float vg = __shfl_sync(0xffffffffu, acc, base + 2);
        float vo = __shfl_sync(0xffffffffu, acc, base + 3);
        float ig = 1.f / (1.f + __expf(-vi));
        float fg = 1.f / (1.f + __expf(-vf));
        float gg = tanhf(vg);
        float og = 1.f / (1.f + __expf(-vo));
        c = fg * c + ig * gg;
        float hv = og * tanhf(c);
        if (gate == 0) {
            int u = u0 + ui;
            seq[(long)(t + 1) * (BB * HD) + (b << 9) + u] = hv;
            out[((long)((b << 9) + sI)) * HH + (dir << 9) + u] = hv;
        }
        __threadfence();
        __syncthreads();
        if (tid == 0) {
            atomicAdd(bar, 1u);
            unsigned target = (unsigned)(t + 1) * 64u;
            while (*((volatile unsigned int*)bar) < target) { }
            __threadfence();
        }
        __syncthreads();
    }
}

extern "C" void kernel_launch(void* const* d_in, const int* in_sizes, int n_in,
                              void* d_out, int out_size)
{
    (void)in_sizes; (void)n_in; (void)out_size;
    const float* x       = (const float*)d_in[0];
    const float* pos_emb = (const float*)d_in[1];
    const float* emb_g   = (const float*)d_in[2];
    const float* emb_b   = (const float*)d_in[3];
    const float* in_w    = (const float*)d_in[4];
    const float* q_bias  = (const float*)d_in[5];
    const float* v_bias  = (const float*)d_in[6];
    const float* rel_emb = (const float*)d_in[7];
    const float* posk_w  = (const float*)d_in[8];
    const float* posq_w  = (const float*)d_in[9];
    const float* posq_b  = (const float*)d_in[10];
    const float* ao_w    = (const float*)d_in[11];
    const float* ao_b    = (const float*)d_in[12];
    const float* aln_g   = (const float*)d_in[13];
    const float* aln_b   = (const float*)d_in[14];
    const float* it_w    = (const float*)d_in[15];
    const float* it_b    = (const float*)d_in[16];
    const float* fo_w    = (const float*)d_in[17];
    const float* fo_b    = (const float*)d_in[18];
    const float* fln_g   = (const float*)d_in[19];
    const float* fln_b   = (const float*)d_in[20];
    const float* Wih_f   = (const float*)d_in[21];
    const float* Whh_f   = (const float*)d_in[22];
    const float* bih_f   = (const float*)d_in[23];
    const float* bhh_f   = (const float*)d_in[24];
    const float* Wih_r   = (const float*)d_in[25];
    const float* Whh_r   = (const float*)d_in[26];
    const float* bih_r   = (const float*)d_in[27];
    const float* bhh_r   = (const float*)d_in[28];
    float* out = (float*)d_out;

    float *h1, *qkv, *posk, *posq, *scores, *ctx2, *t1, *y, *h2, *h3, *xw;
    void  *barp, *seqp;
    cudaGetSymbolAddress((void**)&h1,     g_h1);
    cudaGetSymbolAddress((void**)&qkv,    g_qkv);
    cudaGetSymbolAddress((void**)&posk,   g_posk);
    cudaGetSymbolAddress((void**)&posq,   g_posq);
    cudaGetSymbolAddress((void**)&scores, g_scores);
    cudaGetSymbolAddress((void**)&ctx2,   g_ctx2);
    cudaGetSymbolAddress((void**)&t1,     g_t1);
    cudaGetSymbolAddress((void**)&y,      g_y);
    cudaGetSymbolAddress((void**)&h2,     g_h2);
    cudaGetSymbolAddress((void**)&h3,     g_h3);
    cudaGetSymbolAddress((void**)&xw,     g_xw);
    cudaGetSymbolAddress(&barp,           g_bar2);
    cudaGetSymbolAddress(&seqp,           g_hseq);

    int gsmem = 2 * 128 * PH * 2;   // 20480 B
    cudaFuncSetAttribute(tgemm_kernel, cudaFuncAttributeMaxDynamicSharedMemorySize, gsmem);

    // 1. h1 = LN(x + pos_emb)
    ln_kernel<<<MM, 256>>>(x, pos_emb, SS, emb_g, emb_b, h1);
    // 2. qkv = h1 @ in_w^T
    tgemm_kernel<<<dim3(IN3/128, MM/128), 256, gsmem>>>(h1, in_w, qkv, MM, IN3, HH,
        0, 0, 0, 1.f, 0);
    // 3. pos tables (pos_q pre-scaled)
    tgemm_kernel<<<dim3(HH/128, R2/128), 256, gsmem>>>(rel_emb, posk_w, posk, R2, HH, HH,
        0, 0, 0, 1.f, 0);
    tgemm_kernel<<<dim3(HH/128, R2/128), 256, gsmem>>>(rel_emb, posq_w, posq, R2, HH, HH,
        posq_b, 0, 0, INV_SCALE, 0);
    // 4. fused scores + c2p + p2c + softmax
    attn_kernel<<<BB*NHH*SS, 256>>>(qkv, posk, posq, scores, q_bias);
    // 5. ctx directly from qkv
    ctx_naive_kernel<<<BB*NHH*SS, 128>>>(qkv, scores, ctx2, v_bias);
    // 6. attn out + residual + LN
    tgemm_kernel<<<dim3(HH/128, MM/128), 256, gsmem>>>(ctx2, ao_w, y, MM, HH, HH,
        ao_b, 0, h1, 1.f, 0);
    ln_kernel<<<MM, 256>>>(y, 0, 1, aln_g, aln_b, h2);
    // 7. FFN
    tgemm_kernel<<<dim3(IN3/128, MM/128), 256, gsmem>>>(h2, it_w, t1, MM, IN3, HH,
        it_b, 0, 0, 1.f, 1);
    tgemm_kernel<<<dim3(HH/128, MM/128), 256, gsmem>>>(t1, fo_w, y, MM, HH, IN3,
        fo_b, 0, h2, 1.f, 0);
    ln_kernel<<<MM, 256>>>(y, 0, 1, fln_g, fln_b, h3);
    // 8. LSTM input projections
    tgemm_kernel<<<dim3(G4/128, MM/128), 256, gsmem>>>(h3, Wih_f, xw, MM, G4, HH,
        bih_f, bhh_f, 0, 1.f, 0);
    tgemm_kernel<<<dim3(G4/128, MM/128), 256, gsmem>>>(h3, Wih_r, xw + (long)MM*G4, MM, G4, HH,
        bih_r, bhh_r, 0, 1.f, 0);
    // 9. persistent wavefront LSTM
    cudaMemsetAsync(barp, 0, 2 * sizeof(unsigned int), 0);
    cudaMemsetAsync(seqp, 0, sizeof(float) * BB * HD, 0);
    cudaMemsetAsync((char*)seqp + sizeof(float) * 513 * BB * HD, 0, sizeof(float) * BB * HD, 0);
    int lsmem = HD * 32 * 4 + BB * HD * 4;
    cudaFuncSetAttribute(LSTMDisentangledAttention_15049565405471_kernel,
                         cudaFuncAttributeMaxDynamicSharedMemorySize, lsmem);
    LSTMDisentangledAttention_15049565405471_kernel<<<128, 256, lsmem>>>(xw, Whh_f, Whh_r, out);
}

// round 17
// speedup vs baseline: 1.0913x; 1.0158x over previous
#include <cuda_runtime.h>
#include <cuda_fp16.h>
#include <math.h>

#define BB   8
#define SS   512
#define HH   1024
#define NHH  8
#define DHH  128
#define MM   (BB*SS)
#define IN3  3072
#define R2   1024
#define HD   512
#define G4   2048
#define INV_SCALE 0.051031036307982884f  /* 1/sqrt(128*3) */
#define PH   40                          /* smem pitch in halfs */
#define TILE_H (128 * PH)               /* halfs per buffer per matrix */

__device__ float g_h1[MM*HH];
__device__ float g_qkv[MM*3*HH];
__device__ float g_posk[R2*HH];
__device__ float g_posq[R2*HH];
__device__ float g_scores[BB*NHH*SS*SS];
__device__ float g_ctx2[MM*HH];
__device__ float g_t1[MM*IN3];
__device__ float g_y[MM*HH];
__device__ float g_h2[MM*HH];
__device__ float g_h3[MM*HH];
__device__ float g_xw[2*MM*G4];
__device__ float g_hseq[2*513*BB*HD];
__device__ unsigned int g_bar2[2];

// Tensor-core GEMM: C = A[M,K]*B[N,K]^T via mma.m16n8k16 f16 (fp32 accum).
// 128x128 block tile, 8 warps (2x4), warp 64x32. K-tile 16, DOUBLE-buffered smem,
// one __syncthreads per tile, register-staged fp32->fp16 conversion.
__global__ void __launch_bounds__(256, 2)
tgemm_kernel(const float* __restrict__ A, const float* __restrict__ Bw,
             float* __restrict__ C, int Md, int Nd, int Kd,
             const float* __restrict__ bias, const float* __restrict__ bias2,
             const float* __restrict__ res, float scale, int act)
{
    extern __shared__ char smraw[];
    __half* Ah = (__half*)smraw;                            // [2][128][PH]
    __half* Bh = (__half*)(smraw + 2 * TILE_H * 2);         // [2][128][PH]
    int tid = threadIdx.x;
    int m0 = blockIdx.y << 7, n0 = blockIdx.x << 7;
    int warp = tid >> 5, lane = tid & 31;
    int wm = (warp >> 2) << 6;
    int wn = (warp & 3) << 5;
    int g = lane >> 2, tg = lane & 3;

    float c[4][4][4];
#pragma unroll
    for (int mt = 0; mt < 4; mt++)
#pragma unroll
        for (int nt = 0; nt < 4; nt++)
#pragma unroll
            for (int i = 0; i < 4; i++) c[mt][nt][i] = 0.f;

    float4 pa[2], pb[2];
    auto ldg_tile = [&](int k0) {
#pragma unroll
        for (int i = 0; i < 2; i++) {
            int ch = tid + (i << 8);
            int row = ch >> 2, kq = (ch & 3) << 2;
            pa[i] = *(const float4*)(A  + (long)(m0 + row) * Kd + k0 + kq);
            pb[i] = *(const float4*)(Bw + (long)(n0 + row) * Kd + k0 + kq);
        }
    };
    auto sts_tile = [&](int st) {
#pragma unroll
        for (int i = 0; i < 2; i++) {
            int ch = tid + (i << 8);
            int row = ch >> 2, kq = (ch & 3) << 2;
            __half2* da = (__half2*)(Ah + st * TILE_H + row * PH + kq);
            da[0] = __floats2half2_rn(pa[i].x, pa[i].y);
            da[1] = __floats2half2_rn(pa[i].z, pa[i].w);
            __half2* db = (__half2*)(Bh + st * TILE_H + row * PH + kq);
            db[0] = __floats2half2_rn(pb[i].x, pb[i].y);
            db[1] = __floats2half2_rn(pb[i].z, pb[i].w);
        }
    };

    int nk = Kd >> 4;
    ldg_tile(0);
    sts_tile(0);
    if (nk > 1) ldg_tile(16);
    __syncthreads();

    for (int kt = 0; kt < nk; kt++) {
        const unsigned* Au = (const unsigned*)(Ah + (kt & 1) * TILE_H);
        const unsigned* Bu = (const unsigned*)(Bh + (kt & 1) * TILE_H);
        unsigned af[4][4], bf[4][2];
#pragma unroll
        for (int mt = 0; mt < 4; mt++) {
            int r = wm + (mt << 4) + g;
            af[mt][0] = Au[r * (PH / 2) + tg];
            af[mt][1] = Au[(r + 8) * (PH / 2) + tg];
            af[mt][2] = Au[r * (PH / 2) + tg + 4];
            af[mt][3] = Au[(r + 8) * (PH / 2) + tg + 4];
        }
#pragma unroll
        for (int nt = 0; nt < 4; nt++) {
            int r = wn + (nt << 3) + g;
            bf[nt][0] = Bu[r * (PH / 2) + tg];
            bf[nt][1] = Bu[r * (PH / 2) + tg + 4];
        }
#pragma unroll
        for (int mt = 0; mt < 4; mt++)
#pragma unroll
            for (int nt = 0; nt < 4; nt++) {
                asm volatile(
                    "mma.sync.aligned.m16n8k16.row.col.f32.f16.f16.f32 "
                    "{%0,%1,%2,%3}, {%4,%5,%6,%7}, {%8,%9}, {%0,%1,%2,%3};"
                    : "+f"(c[mt][nt][0]), "+f"(c[mt][nt][1]),
                      "+f"(c[mt][nt][2]), "+f"(c[mt][nt][3])
                    : "r"(af[mt][0]), "r"(af[mt][1]), "r"(af[mt][2]), "r"(af[mt][3]),
                      "r"(bf[nt][0]), "r"(bf[nt][1]));
            }
        if (kt + 1 < nk) {
            sts_tile((kt + 1) & 1);            // from regs of tile kt+1
            if (kt + 2 < nk) ldg_tile((kt + 2) << 4);  // hides under next compute
        }
        __syncthreads();
    }

#pragma unroll
    for (int mt = 0; mt < 4; mt++) {
#pragma unroll
        for (int nt = 0; nt < 4; nt++) {
#pragma unroll
            for (int i = 0; i < 4; i++) {
                int m = m0 + wm + (mt << 4) + g + ((i >> 1) << 3);
                int n = n0 + wn + (nt << 3) + (tg << 1) + (i & 1);
                float v = c[mt][nt][i];
                if (bias)  v += bias[n];
                if (bias2) v += bias2[n];
                if (res)   v += res[(long)m * Nd + n];
                v *= scale;
                if (act) v = 0.5f * v * (1.f + erff(v * 0.70710678118654752f));
                C[(long)m * Nd + n] = v;
            }
        }
    }
}

// LN with optional fused add (pos-emb broadcast over batch via addMod)
__global__ void ln_kernel(const float* __restrict__ in, const float* __restrict__ add,
                          int addMod, const float* __restrict__ gw,
                          const float* __restrict__ bw, float* __restrict__ out)
{
    int row = blockIdx.x;
    const float* xp = in + (long)row * HH;
    const float* ap = add ? add + (long)(row % addMod) * HH : (const float*)0;
    int tid = threadIdx.x;
    float v[4]; float s = 0.f, sq = 0.f;
#pragma unroll
    for (int i = 0; i < 4; i++) {
        int c = tid + (i << 8);
        float t = xp[c];
        if (ap) t += ap[c];
        v[i] = t; s += t; sq += t * t;
    }
#pragma unroll
    for (int o = 16; o > 0; o >>= 1) {
        s  += __shfl_xor_sync(0xffffffffu, s, o);
        sq += __shfl_xor_sync(0xffffffffu, sq, o);
    }
    __shared__ float red[18];
    int w = tid >> 5, l = tid & 31;
    if (l == 0) { red[w] = s; red[8 + w] = sq; }
    __syncthreads();
    if (tid == 0) {
        float ts = 0.f, tq = 0.f;
#pragma unroll
        for (int i = 0; i < 8; i++) { ts += red[i]; tq += red[8 + i]; }
        float mean = ts * (1.f / HH);
        float var  = tq * (1.f / HH) - mean * mean;
        red[16] = mean; red[17] = rsqrtf(var + 1e-7f);
    }
    __syncthreads();
    float mean = red[16], rstd = red[17];
    float* op = out + (long)row * HH;
#pragma unroll
    for (int i = 0; i < 4; i++) {
        int c = tid + (i << 8);
        op[c] = (v[i] - mean) * rstd * gw[c] + bw[c];
    }
}

// Fused scores + c2p + p2c + softmax, coalesced warp-per-k.
__global__ void attn_kernel(const float* __restrict__ qkv, const float* __restrict__ posk,
                            const float* __restrict__ posq, float* __restrict__ scores,
                            const float* __restrict__ qb)
{
    int row = blockIdx.x;
    int z = row >> 9, q = row & 511;
    int b = z >> 3, h = z & 7;
    int tid = threadIdx.x;
    int w = tid >> 5, lane = tid & 31;
    __shared__ float qs[DHH];
    __shared__ float sc[SS];
    __shared__ float red[17];
    const float* qkvq = qkv + ((long)(b * SS + q)) * (3 * HH) + h * DHH;
    if (tid < DHH) qs[tid] = (qkvq[tid] + qb[h * DHH + tid]) * INV_SCALE;
    __syncthreads();
    float4 qv = ((const float4*)qs)[lane];

#pragma unroll 2
    for (int i = 0; i < 64; i++) {
        int k = (w << 6) + i;
        int rel = q - k + 512;
        float4 kv = ((const float4*)(qkv + ((long)(b * SS + k)) * (3 * HH) + HH + h * DHH))[lane];
        float4 cv = ((const float4*)(posk + (long)rel * HH + h * DHH))[lane];
        float4 pv = ((const float4*)(posq + (long)rel * HH + h * DHH))[lane];
        float s = qv.x * (kv.x + cv.x) + kv.x * pv.x
                + qv.y * (kv.y + cv.y) + kv.y * pv.y
                + qv.z * (kv.z + cv.z) + kv.z * pv.z
                + qv.w * (kv.w + cv.w) + kv.w * pv.w;
#pragma unroll
        for (int o = 16; o > 0; o >>= 1) s += __shfl_xor_sync(0xffffffffu, s, o);
        if (lane == 0) sc[k] = s;
    }
    __syncthreads();

    float v0 = sc[tid], v1 = sc[tid + 256];
    float mx = fmaxf(v0, v1);
#pragma unroll
    for (int o = 16; o > 0; o >>= 1) mx = fmaxf(mx, __shfl_xor_sync(0xffffffffu, mx, o));
    if (lane == 0) red[w] = mx;
    __syncthreads();
    if (tid == 0) {
        float m2 = red[0];
#pragma unroll
        for (int i = 1; i < 8; i++) m2 = fmaxf(m2, red[i]);
        red[16] = m2;
    }
    __syncthreads();
    mx = red[16];
    float e0 = __expf(v0 - mx), e1 = __expf(v1 - mx);
    float s = e0 + e1;
#pragma unroll
    for (int o = 16; o > 0; o >>= 1) s += __shfl_xor_sync(0xffffffffu, s, o);
    __syncthreads();
    if (lane == 0) red[w] = s;
    __syncthreads();
    if (tid == 0) {
        float t = 0.f;
#pragma unroll
        for (int i = 0; i < 8; i++) t += red[i];
        red[16] = 1.f / t;
    }
    __syncthreads();
    float inv = red[16];
    float* srow = scores + (long)row * SS;
    srow[tid] = e0 * inv;
    srow[tid + 256] = e1 * inv;
}

// ctx2[b,q,h*128+d] = sum_k probs[z,q,k] * qkv_v[b,k,h*128+d]  + vb
__global__ void ctx_naive_kernel(const float* __restrict__ qkv, const float* __restrict__ scores,
                                 float* __restrict__ ctx2, const float* __restrict__ vb)
{
    __shared__ float ps[SS];
    int row = blockIdx.x;
    int z = row >> 9, q = row & 511;
    int b = z >> 3, h = z & 7;
    int tid = threadIdx.x;
    const float* srow = scores + (long)row * SS;
    for (int k = tid; k < SS; k += 128) ps[k] = srow[k];
    __syncthreads();
    int c = h * DHH + tid;
    const float* vp = qkv + (long)b * SS * (3 * HH) + 2 * HH + c;
    float acc = 0.f;
#pragma unroll 4
    for (int k = 0; k < SS; k++)
        acc = fmaf(ps[k], vp[(long)k * (3 * HH)], acc);
    acc += vb[c];
    ctx2[((long)(b * SS + q)) * HH + c] = acc;
}

// Persistent wavefront LSTM: 128 blocks, per-direction barriers, float4 weight/h loads.
__global__ void LSTMDisentangledAttention_15049565405471_kernel(
    const float* __restrict__ xw,
    const float* __restrict__ WhhF,
    const float* __restrict__ WhhR,
    float* __restrict__ out)
{
    extern __shared__ float sm[];
    float* Wsh = sm;              // [128][32][4]
    float* hs  = sm + HD * 32;    // [8][512]
    int tid = threadIdx.x, blk = blockIdx.x;
    int dir = blk >> 6;
    int u0  = (blk & 63) << 3;
    int b = tid >> 5, lane = tid & 31;
    int ui = lane >> 2, gate = lane & 3;
    int r = (gate << 9) + u0 + ui;
    const float* Whh = dir ? WhhR : WhhF;
    const float* xwd = xw + (long)dir * MM * G4;
    float* seq = g_hseq + (long)dir * 513 * (BB * HD);
    unsigned int* bar = &g_bar2[dir];

    for (int idx = tid; idx < HD * 32; idx += 256) {
        int jb = idx >> 7;
        int l  = (idx >> 2) & 31;
        int jj = idx & 3;
        int j  = (jb << 2) + jj;
        int rl = ((l & 3) << 9) + u0 + (l >> 2);
        Wsh[idx] = Whh[(long)rl * HD + j];
    }

    float c = 0.f;
    __syncthreads();

    const float4* W4 = (const float4*)Wsh;
    for (int t = 0; t < SS; t++) {
        int sI = dir ? (SS - 1 - t) : t;
        const float* hrd = seq + (long)t * (BB * HD);
        for (int idx = tid; idx < BB * HD; idx += 256)
            hs[idx] = hrd[idx];
        __syncthreads();

        float acc = xwd[((long)((b << 9) + sI)) * G4 + r];
        const float4* h4 = (const float4*)(hs + (b << 9));
#pragma unroll 8
        for (int jb = 0; jb < 128; jb++) {
            float4 wv = W4[(jb << 5) + lane];
            float4 hv = h4[jb];
            acc = fmaf(wv.x, hv.x, acc);
            acc = fmaf(wv.y, hv.y, acc);
            acc = fmaf(wv.z, hv.z, acc);
            acc = fmaf(wv.w, hv.w, acc);
        }

        int base = lane & ~3;
        float vi = __shfl_sync(0xffffffffu, acc, base + 0);
        float vf = __shfl_sync(0xffffffffu, acc, base + 1);
        float vg = __shfl_sync(0xffffffffu, acc, base + 2);
        float vo = __shfl_sync(0xffffffffu, acc, base + 3);
        float ig = 1.f / (1.f + __expf(-vi));
        float fg = 1.f / (1.f + __expf(-vf));
        float gg = tanhf(vg);
        float og = 1.f / (1.f + __expf(-vo));
        c = fg * c + ig * gg;
        float hv = og * tanhf(c);
        if (gate == 0) {
            int u = u0 + ui;
            seq[(long)(t + 1) * (BB * HD) + (b << 9) + u] = hv;
            out[((long)((b << 9) + sI)) * HH + (dir << 9) + u] = hv;
        }
        __threadfence();
        __syncthreads();
        if (tid == 0) {
            atomicAdd(bar, 1u);
            unsigned target = (unsigned)(t + 1) * 64u;
            while (*((volatile unsigned int*)bar) < target) { }
            __threadfence();
        }
        __syncthreads();
    }
}

extern "C" void kernel_launch(void* const* d_in, const int* in_sizes, int n_in,
                              void* d_out, int out_size)
{
    (void)in_sizes; (void)n_in; (void)out_size;
    const float* x       = (const float*)d_in[0];
    const float* pos_emb = (const float*)d_in[1];
    const float* emb_g   = (const float*)d_in[2];
    const float* emb_b   = (const float*)d_in[3];
    const float* in_w    = (const float*)d_in[4];
    const float* q_bias  = (const float*)d_in[5];
    const float* v_bias  = (const float*)d_in[6];
    const float* rel_emb = (const float*)d_in[7];
    const float* posk_w  = (const float*)d_in[8];
    const float* posq_w  = (const float*)d_in[9];
    const float* posq_b  = (const float*)d_in[10];
    const float* ao_w    = (const float*)d_in[11];
    const float* ao_b    = (const float*)d_in[12];
    const float* aln_g   = (const float*)d_in[13];
    const float* aln_b   = (const float*)d_in[14];
    const float* it_w    = (const float*)d_in[15];
    const float* it_b    = (const float*)d_in[16];
    const float* fo_w    = (const float*)d_in[17];
    const float* fo_b    = (const float*)d_in[18];
    const float* fln_g   = (const float*)d_in[19];
    const float* fln_b   = (const float*)d_in[20];
    const float* Wih_f   = (const float*)d_in[21];
    const float* Whh_f   = (const float*)d_in[22];
    const float* bih_f   = (const float*)d_in[23];
    const float* bhh_f   = (const float*)d_in[24];
    const float* Wih_r   = (const float*)d_in[25];
    const float* Whh_r   = (const float*)d_in[26];
    const float* bih_r   = (const float*)d_in[27];
    const float* bhh_r   = (const float*)d_in[28];
    float* out = (float*)d_out;

    float *h1, *qkv, *posk, *posq, *scores, *ctx2, *t1, *y, *h2, *h3, *xw;
    void  *barp, *seqp;
    cudaGetSymbolAddress((void**)&h1,     g_h1);
    cudaGetSymbolAddress((void**)&qkv,    g_qkv);
    cudaGetSymbolAddress((void**)&posk,   g_posk);
    cudaGetSymbolAddress((void**)&posq,   g_posq);
    cudaGetSymbolAddress((void**)&scores, g_scores);
    cudaGetSymbolAddress((void**)&ctx2,   g_ctx2);
    cudaGetSymbolAddress((void**)&t1,     g_t1);
    cudaGetSymbolAddress((void**)&y,      g_y);
    cudaGetSymbolAddress((void**)&h2,     g_h2);
    cudaGetSymbolAddress((void**)&h3,     g_h3);
    cudaGetSymbolAddress((void**)&xw,     g_xw);
    cudaGetSymbolAddress(&barp,           g_bar2);
    cudaGetSymbolAddress(&seqp,           g_hseq);

    int gsmem = 2 * 2 * TILE_H * 2;   // 40960 B -> 2 blocks/SM
    cudaFuncSetAttribute(tgemm_kernel, cudaFuncAttributeMaxDynamicSharedMemorySize, gsmem);

    // 1. h1 = LN(x + pos_emb)
    ln_kernel<<<MM, 256>>>(x, pos_emb, SS, emb_g, emb_b, h1);
    // 2. qkv = h1 @ in_w^T
    tgemm_kernel<<<dim3(IN3/128, MM/128), 256, gsmem>>>(h1, in_w, qkv, MM, IN3, HH,
        0, 0, 0, 1.f, 0);
    // 3. pos tables (pos_q pre-scaled)
    tgemm_kernel<<<dim3(HH/128, R2/128), 256, gsmem>>>(rel_emb, posk_w, posk, R2, HH, HH,
        0, 0, 0, 1.f, 0);
    tgemm_kernel<<<dim3(HH/128, R2/128), 256, gsmem>>>(rel_emb, posq_w, posq, R2, HH, HH,
        posq_b, 0, 0, INV_SCALE, 0);
    // 4. fused scores + c2p + p2c + softmax
    attn_kernel<<<BB*NHH*SS, 256>>>(qkv, posk, posq, scores, q_bias);
    // 5. ctx directly from qkv
    ctx_naive_kernel<<<BB*NHH*SS, 128>>>(qkv, scores, ctx2, v_bias);
    // 6. attn out + residual + LN
    tgemm_kernel<<<dim3(HH/128, MM/128), 256, gsmem>>>(ctx2, ao_w, y, MM, HH, HH,
        ao_b, 0, h1, 1.f, 0);
    ln_kernel<<<MM, 256>>>(y, 0, 1, aln_g, aln_b, h2);
    // 7. FFN
    tgemm_kernel<<<dim3(IN3/128, MM/128), 256, gsmem>>>(h2, it_w, t1, MM, IN3, HH,
        it_b, 0, 0, 1.f, 1);
    tgemm_kernel<<<dim3(HH/128, MM/128), 256, gsmem>>>(t1, fo_w, y, MM, HH, IN3,
        fo_b, 0, h2, 1.f, 0);
    ln_kernel<<<MM, 256>>>(y, 0, 1, fln_g, fln_b, h3);
    // 8. LSTM input projections
    tgemm_kernel<<<dim3(G4/128, MM/128), 256, gsmem>>>(h3, Wih_f, xw, MM, G4, HH,
        bih_f, bhh_f, 0, 1.f, 0);
    tgemm_kernel<<<dim3(G4/128, MM/128), 256, gsmem>>>(h3, Wih_r, xw + (long)MM*G4, MM, G4, HH,
        bih_r, bhh_r, 0, 1.f, 0);
    // 9. persistent wavefront LSTM
    cudaMemsetAsync(barp, 0, 2 * sizeof(unsigned int), 0);
    cudaMemsetAsync(seqp, 0, sizeof(float) * BB * HD, 0);
    cudaMemsetAsync((char*)seqp + sizeof(float) * 513 * BB * HD, 0, sizeof(float) * BB * HD, 0);
    int lsmem = HD * 32 * 4 + BB * HD * 4;
    cudaFuncSetAttribute(LSTMDisentangledAttention_15049565405471_kernel,
                         cudaFuncAttributeMaxDynamicSharedMemorySize, lsmem);
    LSTMDisentangledAttention_15049565405471_kernel<<<128, 256, lsmem>>>(xw, Whh_f, Whh_r, out);
}